// round 6
// baseline (speedup 1.0000x reference)
#include <cuda_runtime.h>
#include <cuda_bf16.h>
#include <math.h>
#include <stdint.h>

#define NB   64
#define NT   256
#define EMBD 512
#define VOCAB 32000
#define RNN  1024
#define Z4   4096
#define HIDN 128
#define NLAB 4

// Column permutation: original n = gate*1024 + j  ->  col' = j*4 + gate.
// UT/WT/XW/zp all live in col' layout; cell tail reads contiguous gate quads.

// ---------------- static device scratch ----------------------------------
__device__ float g_XW[(size_t)NT * NB * Z4];            // emb[x] @ W  (col' layout)
__device__ __nv_bfloat16 g_UThi[(size_t)Z4 * RNN];      // U^T hi, [col'][k]
__device__ __nv_bfloat16 g_UTlo[(size_t)Z4 * RNN];
__device__ __nv_bfloat16 g_WThi[(size_t)Z4 * EMBD];     // W^T hi, [col'][k]
__device__ __nv_bfloat16 g_WTlo[(size_t)Z4 * EMBD];
__device__ __nv_bfloat16 g_Ehi[(size_t)VOCAB * EMBD];
__device__ __nv_bfloat16 g_Elo[(size_t)VOCAB * EMBD];
__device__ __nv_bfloat16 g_Hs[128 * RNN];               // [h_hi(64); h_lo(64)]
__device__ float g_zp[4][NB * Z4];                      // z partials (col' layout)
__device__ float g_c[NB * RNN];
__device__ float g_pooled[NB * RNN];
__device__ int   g_active[NT];
__device__ int   g_zcnt[32];

// ---------------- helpers --------------------------------------------------
__device__ __forceinline__ uint32_t smem_u32(const void* p) {
    return (uint32_t)__cvta_generic_to_shared(p);
}
__device__ __forceinline__ void cp_async16(uint32_t smem_dst, const void* gsrc) {
    asm volatile("cp.async.cg.shared.global [%0], [%1], 16;" :: "r"(smem_dst), "l"(gsrc));
}
#define CP_COMMIT() asm volatile("cp.async.commit_group;" ::: "memory")

__device__ __forceinline__ void ldsm_x4(uint32_t& r0, uint32_t& r1,
                                        uint32_t& r2, uint32_t& r3, uint32_t addr) {
    asm volatile("ldmatrix.sync.aligned.m8n8.x4.shared.b16 {%0,%1,%2,%3}, [%4];"
                 : "=r"(r0), "=r"(r1), "=r"(r2), "=r"(r3) : "r"(addr));
}
__device__ __forceinline__ void mma_bf16(float* c, uint32_t a0, uint32_t a1,
                                         uint32_t a2, uint32_t a3,
                                         uint32_t b0, uint32_t b1) {
    asm volatile("mma.sync.aligned.m16n8k16.row.col.f32.bf16.bf16.f32 "
                 "{%0,%1,%2,%3}, {%4,%5,%6,%7}, {%8,%9}, {%0,%1,%2,%3};"
                 : "+f"(c[0]), "+f"(c[1]), "+f"(c[2]), "+f"(c[3])
                 : "r"(a0), "r"(a1), "r"(a2), "r"(a3), "r"(b0), "r"(b1));
}

// ---------------- prep -----------------------------------------------------
__global__ void prep_kernel(const int* __restrict__ x) {
    int t = threadIdx.x;
    if (t < NT) {
        int act = 0;
        for (int b = 0; b < NB; b++) act |= (x[b * NT + t] != 0);
        g_active[t] = act;
    }
    if (t < 32) g_zcnt[t] = 0;
}

__global__ void zero_kernel() {
    int i = blockIdx.x * blockDim.x + threadIdx.x;
    if (i < NB * RNN) {
        g_c[i] = 0.f; g_pooled[i] = 0.f;
        ((uint32_t*)g_Hs)[i] = 0u;
    }
}

// ---------------- emb split ------------------------------------------------
__global__ __launch_bounds__(256) void esplit_kernel(const float* __restrict__ emb) {
    size_t i = (size_t)blockIdx.x * 256 + threadIdx.x;
    float v = emb[i];
    __nv_bfloat16 hi = __float2bfloat16(v);
    g_Ehi[i] = hi;
    g_Elo[i] = __float2bfloat16(v - __bfloat162float(hi));
}

// ---------------- transpose+split+permute: U and W -------------------------
__device__ __forceinline__ int permute_col(int n) {
    return (n & 1023) * 4 + (n >> 10);
}

__global__ __launch_bounds__(256) void upack_kernel(const float* __restrict__ U) {
    __shared__ float tile[64][65];
    const int k0 = blockIdx.x * 64;
    const int n0 = blockIdx.y * 64;
    const int tid = threadIdx.x;
    #pragma unroll
    for (int it = 0; it < 16; it++) {
        int r = it * 4 + (tid >> 6);
        int c = tid & 63;
        tile[r][c] = U[(size_t)(k0 + r) * Z4 + n0 + c];
    }
    __syncthreads();
    #pragma unroll
    for (int it = 0; it < 16; it++) {
        int n = it * 4 + (tid >> 6);
        int k = tid & 63;
        float v = tile[k][n];
        __nv_bfloat16 hi = __float2bfloat16(v);
        const int np = permute_col(n0 + n);
        g_UThi[(size_t)np * RNN + k0 + k] = hi;
        g_UTlo[(size_t)np * RNN + k0 + k] =
            __float2bfloat16(v - __bfloat162float(hi));
    }
}

__global__ __launch_bounds__(256) void wpack_kernel(const float* __restrict__ W) {
    __shared__ float tile[64][65];
    const int k0 = blockIdx.x * 64;
    const int n0 = blockIdx.y * 64;
    const int tid = threadIdx.x;
    #pragma unroll
    for (int it = 0; it < 16; it++) {
        int r = it * 4 + (tid >> 6);
        int c = tid & 63;
        tile[r][c] = W[(size_t)(k0 + r) * Z4 + n0 + c];
    }
    __syncthreads();
    #pragma unroll
    for (int it = 0; it < 16; it++) {
        int n = it * 4 + (tid >> 6);
        int k = tid & 63;
        float v = tile[k][n];
        __nv_bfloat16 hi = __float2bfloat16(v);
        const int np = permute_col(n0 + n);
        g_WThi[(size_t)np * EMBD + k0 + k] = hi;
        g_WTlo[(size_t)np * EMBD + k0 + k] =
            __float2bfloat16(v - __bfloat162float(hi));
    }
}

// ---------------- shared GEMM core pieces -----------------------------------
#define BUF_BYTES 32768
#define GEMM_SMEM (1024 + 2 * BUF_BYTES)

// warp tiling: 8 warps = 4m x 2n; warp tile m32 (paired hi/lo 16+16) x n64.
// accum c[mt(2)][nt(4)][h(2)][4]; mt0 = hi rows (mw*16), mt1 = lo rows (64+mw*16);
// fold mt0+mt1 in epilogue.

// ---------------- HMMA input projection: XW[t] = emb[x_t] @ W --------------
#define XCHUNKS 16

__global__ __launch_bounds__(256) void xw_mma_kernel(const int* __restrict__ x) {
    const int t = blockIdx.y;
    if (!g_active[t]) return;

    extern __shared__ char dyn[];
    __shared__ int idxs[64];
    const uint32_t tb = (smem_u32(dyn) + 1023u) & ~1023u;

    const int tid  = threadIdx.x;
    const int w    = tid >> 5;
    const int lane = tid & 31;
    const int n0   = blockIdx.x * 128;
    const int mw   = w >> 1;
    const int nw   = w & 1;

    if (tid < 64) idxs[tid] = x[tid * NT + t];
    __syncthreads();

    float c[2][4][2][4];
    #pragma unroll
    for (int i = 0; i < 2; i++)
        #pragma unroll
        for (int j = 0; j < 4; j++)
            #pragma unroll
            for (int h = 0; h < 2; h++)
                #pragma unroll
                for (int r = 0; r < 4; r++) c[i][j][h][r] = 0.f;

    auto load_chunk = [&](int ch, int slot) {
        const uint32_t ab = tb + slot * BUF_BYTES;
        const uint32_t bb = ab + 16384;
        const int pass = ch >> 3;
        const int kg = (ch & 7) * 64;
        const __nv_bfloat16* Bsrc =
            (pass ? g_WTlo : g_WThi) + (size_t)n0 * EMBD + kg;
        #pragma unroll
        for (int r = 0; r < 4; r++) {
            const int o   = tid + 256 * r;
            const int row = o >> 3;
            const int cb  = o & 7;
            uint32_t off = (uint32_t)(row * 128 + cb * 16);
            uint32_t sw  = off ^ ((off >> 3) & 0x70);
            const __nv_bfloat16* asrc =
                (row < 64) ? (g_Ehi + (size_t)idxs[row] * EMBD + kg + cb * 8)
                           : (g_Elo + (size_t)idxs[row - 64] * EMBD + kg + cb * 8);
            cp_async16(ab + sw, asrc);
            cp_async16(bb + sw, Bsrc + (size_t)row * EMBD + cb * 8);
        }
        CP_COMMIT();
    };

    load_chunk(0, 0);

    const int lrow = ((lane >> 3) & 1) * 8 + (lane & 7);
    const int lcolb = (lane >> 4) * 16;

    for (int ch = 0; ch < XCHUNKS; ch++) {
        if (ch + 1 < XCHUNKS) load_chunk(ch + 1, (ch + 1) & 1);
        if (ch + 1 < XCHUNKS) asm volatile("cp.async.wait_group 1;" ::: "memory");
        else                  asm volatile("cp.async.wait_group 0;" ::: "memory");
        __syncthreads();

        const uint32_t ab = tb + (ch & 1) * BUF_BYTES;
        const uint32_t bb = ab + 16384;

        #pragma unroll
        for (int kk = 0; kk < 4; kk++) {
            // B frags: 4 n16 tiles in warp's n64 slice
            uint32_t bf[4][4];
            #pragma unroll
            for (int nt = 0; nt < 4; nt++) {
                uint32_t boff = (uint32_t)((nw * 64 + nt * 16 + lrow) * 128 + kk * 32 + lcolb);
                uint32_t baddr = bb + (boff ^ ((boff >> 3) & 0x70));
                ldsm_x4(bf[nt][0], bf[nt][1], bf[nt][2], bf[nt][3], baddr);
            }
            #pragma unroll
            for (int mt = 0; mt < 2; mt++) {
                const int mbase = mt * 64 + mw * 16;
                uint32_t aoff = (uint32_t)((mbase + lrow) * 128 + kk * 32 + lcolb);
                uint32_t aaddr = ab + (aoff ^ ((aoff >> 3) & 0x70));
                uint32_t a0, a1, a2, a3;
                ldsm_x4(a0, a1, a2, a3, aaddr);
                #pragma unroll
                for (int nt = 0; nt < 4; nt++) {
                    mma_bf16(c[mt][nt][0], a0, a1, a2, a3, bf[nt][0], bf[nt][2]);
                    mma_bf16(c[mt][nt][1], a0, a1, a2, a3, bf[nt][1], bf[nt][3]);
                }
            }
        }
        __syncthreads();
    }

    float* C = g_XW + (size_t)t * NB * Z4;
    #pragma unroll
    for (int nt = 0; nt < 4; nt++) {
        #pragma unroll
        for (int h = 0; h < 2; h++) {
            const int row = mw * 16 + (lane >> 2);
            const int col = n0 + nw * 64 + nt * 16 + h * 8 + (lane & 3) * 2;
            float2 v01 = make_float2(c[0][nt][h][0] + c[1][nt][h][0],
                                     c[0][nt][h][1] + c[1][nt][h][1]);
            float2 v23 = make_float2(c[0][nt][h][2] + c[1][nt][h][2],
                                     c[0][nt][h][3] + c[1][nt][h][3]);
            *reinterpret_cast<float2*>(C + (size_t)row * Z4 + col) = v01;
            *reinterpret_cast<float2*>(C + (size_t)(row + 8) * Z4 + col) = v23;
        }
    }
}

// ---------------- per-step fused GEMM + cell --------------------------------
// grid (32 n-groups, 2 s, 2 ks) x 256. Block: M=128 (hi/lo), N=128, K=512.
// Last of the 4 partial blocks per n-group does the LSTM cell update.
#define ZCHUNKS 8

__global__ __launch_bounds__(256) void zstep_kernel(const int* __restrict__ x,
                                                    const float* __restrict__ bias, int t) {
    if (!g_active[t]) return;

    extern __shared__ char dyn[];
    __shared__ int s_last;
    const uint32_t tb = (smem_u32(dyn) + 1023u) & ~1023u;

    const int tid  = threadIdx.x;
    const int w    = tid >> 5;
    const int lane = tid & 31;
    const int ng   = blockIdx.x;
    const int n0   = ng * 128;
    const int s    = blockIdx.y;
    const int ks   = blockIdx.z;
    const int kbase = ks * 512;
    const int mw   = w >> 1;
    const int nw   = w & 1;

    const __nv_bfloat16* Bsrc = (s ? g_UTlo : g_UThi) + (size_t)n0 * RNN;

    float c[2][4][2][4];
    #pragma unroll
    for (int i = 0; i < 2; i++)
        #pragma unroll
        for (int j = 0; j < 4; j++)
            #pragma unroll
            for (int h = 0; h < 2; h++)
                #pragma unroll
                for (int r = 0; r < 4; r++) c[i][j][h][r] = 0.f;

    auto load_chunk = [&](int ch, int slot) {
        const uint32_t ab = tb + slot * BUF_BYTES;
        const uint32_t bb = ab + 16384;
        const int kg = kbase + ch * 64;
        #pragma unroll
        for (int r = 0; r < 4; r++) {
            const int o   = tid + 256 * r;
            const int row = o >> 3;
            const int cb  = o & 7;
            uint32_t off = (uint32_t)(row * 128 + cb * 16);
            uint32_t sw  = off ^ ((off >> 3) & 0x70);
            cp_async16(ab + sw, g_Hs + (size_t)row * RNN + kg + cb * 8);
            cp_async16(bb + sw, Bsrc + (size_t)row * RNN + kg + cb * 8);
        }
        CP_COMMIT();
    };

    load_chunk(0, 0);

    const int lrow = ((lane >> 3) & 1) * 8 + (lane & 7);
    const int lcolb = (lane >> 4) * 16;

    for (int ch = 0; ch < ZCHUNKS; ch++) {
        if (ch + 1 < ZCHUNKS) load_chunk(ch + 1, (ch + 1) & 1);
        if (ch + 1 < ZCHUNKS) asm volatile("cp.async.wait_group 1;" ::: "memory");
        else                  asm volatile("cp.async.wait_group 0;" ::: "memory");
        __syncthreads();

        const uint32_t ab = tb + (ch & 1) * BUF_BYTES;
        const uint32_t bb = ab + 16384;

        #pragma unroll
        for (int kk = 0; kk < 4; kk++) {
            uint32_t bf[4][4];
            #pragma unroll
            for (int nt = 0; nt < 4; nt++) {
                uint32_t boff = (uint32_t)((nw * 64 + nt * 16 + lrow) * 128 + kk * 32 + lcolb);
                uint32_t baddr = bb + (boff ^ ((boff >> 3) & 0x70));
                ldsm_x4(bf[nt][0], bf[nt][1], bf[nt][2], bf[nt][3], baddr);
            }
            #pragma unroll
            for (int mt = 0; mt < 2; mt++) {
                const int mbase = mt * 64 + mw * 16;
                uint32_t aoff = (uint32_t)((mbase + lrow) * 128 + kk * 32 + lcolb);
                uint32_t aaddr = ab + (aoff ^ ((aoff >> 3) & 0x70));
                uint32_t a0, a1, a2, a3;
                ldsm_x4(a0, a1, a2, a3, aaddr);
                #pragma unroll
                for (int nt = 0; nt < 4; nt++) {
                    mma_bf16(c[mt][nt][0], a0, a1, a2, a3, bf[nt][0], bf[nt][2]);
                    mma_bf16(c[mt][nt][1], a0, a1, a2, a3, bf[nt][1], bf[nt][3]);
                }
            }
        }
        __syncthreads();
    }

    // write partials (fold hi/lo rows)
    float* zb = g_zp[s * 2 + ks];
    #pragma unroll
    for (int nt = 0; nt < 4; nt++) {
        #pragma unroll
        for (int h = 0; h < 2; h++) {
            const int row = mw * 16 + (lane >> 2);
            const int col = n0 + nw * 64 + nt * 16 + h * 8 + (lane & 3) * 2;
            float2 v01 = make_float2(c[0][nt][h][0] + c[1][nt][h][0],
                                     c[0][nt][h][1] + c[1][nt][h][1]);
            float2 v23 = make_float2(c[0][nt][h][2] + c[1][nt][h][2],
                                     c[0][nt][h][3] + c[1][nt][h][3]);
            *reinterpret_cast<float2*>(zb + (size_t)row * Z4 + col) = v01;
            *reinterpret_cast<float2*>(zb + (size_t)(row + 8) * Z4 + col) = v23;
        }
    }

    __threadfence();
    __syncthreads();
    if (tid == 0) {
        int old = atomicAdd(&g_zcnt[ng], 1);
        s_last = (old == 3);
    }
    __syncthreads();
    if (!s_last) return;
    if (tid == 0) g_zcnt[ng] = 0;

    // ---- fused cell update for units [ng*32, ng*32+32), all 64 batches ----
    #pragma unroll
    for (int it = 0; it < 8; it++) {
        const int cell = tid + 256 * it;       // 0..2047
        const int b  = cell >> 5;              // 0..63
        const int jl = cell & 31;              // 0..31
        const int j  = ng * 32 + jl;
        const int cb = n0 + jl * 4;            // col' base for this unit

        float4 zv = *reinterpret_cast<const float4*>(
            g_XW + ((size_t)t * NB + b) * Z4 + cb);
        #pragma unroll
        for (int p = 0; p < 4; p++) {
            float4 pv = *reinterpret_cast<const float4*>(
                g_zp[p] + (size_t)b * Z4 + cb);
            zv.x += pv.x; zv.y += pv.y; zv.z += pv.z; zv.w += pv.w;
        }
        const float zi = zv.x + bias[j];
        const float zf = zv.y + bias[RNN + j];
        const float zg = zv.z + bias[2 * RNN + j];
        const float zo = zv.w + bias[3 * RNN + j];

        const float si = 1.f / (1.f + expf(-zi));
        const float sf = 1.f / (1.f + expf(-zf));
        const float so = 1.f / (1.f + expf(-zo));
        const int gi = b * RNN + j;
        const float cn = sf * g_c[gi] + si * tanhf(zg);
        const float hn = so * tanhf(cn);
        const int xv = x[b * NT + t];
        if (xv != 0) {
            g_c[gi] = cn;
            __nv_bfloat16 hi = __float2bfloat16(hn);
            g_Hs[b * RNN + j] = hi;
            g_Hs[(b + 64) * RNN + j] = __float2bfloat16(hn - __bfloat162float(hi));
        }
        if (xv == 2) g_pooled[gi] += hn;
    }
}

// ---------------- head -----------------------------------------------------
__global__ __launch_bounds__(128) void head_kernel(const float* __restrict__ W1,
                                                   const float* __restrict__ b1,
                                                   const float* __restrict__ W2,
                                                   const float* __restrict__ b2,
                                                   const float* __restrict__ Wc,
                                                   const float* __restrict__ bc,
                                                   float* __restrict__ out) {
    const int b = blockIdx.x;
    const int tid = threadIdx.x;
    __shared__ float sp[RNN];
    __shared__ float h1s[HIDN];
    __shared__ float h2s[HIDN];
    __shared__ float lg[NLAB];

    for (int k = tid; k < RNN; k += 128) sp[k] = g_pooled[(size_t)b * RNN + k];
    __syncthreads();

    float a = b1[tid];
    for (int k = 0; k < RNN; k++) a += sp[k] * W1[(size_t)k * HIDN + tid];
    h1s[tid] = fmaxf(a, 0.f);
    __syncthreads();

    float a2 = b2[tid];
    for (int k = 0; k < HIDN; k++) a2 += h1s[k] * W2[(size_t)k * HIDN + tid];
    h2s[tid] = fmaxf(a2, 0.f);
    __syncthreads();

    if (tid < NLAB) {
        float l = bc[tid];
        for (int k = 0; k < HIDN; k++) l += h2s[k] * Wc[(size_t)k * NLAB + tid];
        lg[tid] = l;
    }
    __syncthreads();
    if (tid == 0) {
        const float mx = fmaxf(fmaxf(lg[0], lg[1]), fmaxf(lg[2], lg[3]));
        const float e0 = expf(lg[0] - mx), e1 = expf(lg[1] - mx);
        const float e2 = expf(lg[2] - mx), e3 = expf(lg[3] - mx);
        const float sden = e0 + e1 + e2 + e3;
        out[b * 4 + 0] = e0 / sden; out[b * 4 + 1] = e1 / sden;
        out[b * 4 + 2] = e2 / sden; out[b * 4 + 3] = e3 / sden;
    }
}

// ---------------- launcher -------------------------------------------------
extern "C" void kernel_launch(void* const* d_in, const int* in_sizes, int n_in,
                              void* d_out, int out_size) {
    const int*   x    = (const int*)d_in[0];
    const float* emb  = (const float*)d_in[1];
    const float* W    = (const float*)d_in[2];
    const float* U    = (const float*)d_in[3];
    const float* bias = (const float*)d_in[4];
    const float* W1   = (const float*)d_in[5];
    const float* b1   = (const float*)d_in[6];
    const float* W2   = (const float*)d_in[7];
    const float* b2   = (const float*)d_in[8];
    const float* Wc   = (const float*)d_in[9];
    const float* bc   = (const float*)d_in[10];
    float* out = (float*)d_out;

    cudaFuncSetAttribute(zstep_kernel, cudaFuncAttributeMaxDynamicSharedMemorySize, GEMM_SMEM);
    cudaFuncSetAttribute(xw_mma_kernel, cudaFuncAttributeMaxDynamicSharedMemorySize, GEMM_SMEM);

    prep_kernel<<<1, 256>>>(x);
    zero_kernel<<<256, 256>>>();
    esplit_kernel<<<(VOCAB * EMBD) / 256, 256>>>(emb);
    upack_kernel<<<dim3(RNN / 64, Z4 / 64), 256>>>(U);
    wpack_kernel<<<dim3(EMBD / 64, Z4 / 64), 256>>>(W);
    xw_mma_kernel<<<dim3(32, NT), 256, GEMM_SMEM>>>(x);
    for (int t = 0; t < NT; t++) {
        zstep_kernel<<<dim3(32, 2, 2), 256, GEMM_SMEM>>>(x, bias, t);
    }
    head_kernel<<<NB, 128>>>(W1, b1, W2, b2, Wc, bc, out);
}

// round 7
// speedup vs baseline: 1.2386x; 1.2386x over previous
#include <cuda_runtime.h>
#include <cuda_bf16.h>
#include <math.h>
#include <stdint.h>

#define NB   64
#define NT   256
#define EMBD 512
#define VOCAB 32000
#define RNN  1024
#define Z4   4096
#define HIDN 128
#define NLAB 4

// Column permutation: original n = gate*1024 + j  ->  col' = j*4 + gate.
// UT/WT/XW/zp all live in col' layout; cell tail reads contiguous gate quads.

// ---------------- static device scratch ----------------------------------
__device__ float g_XW[(size_t)NT * NB * Z4];            // emb[x] @ W  (col' layout)
__device__ __nv_bfloat16 g_UThi[(size_t)Z4 * RNN];      // U^T hi, [col'][k]
__device__ __nv_bfloat16 g_UTlo[(size_t)Z4 * RNN];
__device__ __nv_bfloat16 g_WThi[(size_t)Z4 * EMBD];     // W^T hi, [col'][k]
__device__ __nv_bfloat16 g_WTlo[(size_t)Z4 * EMBD];
__device__ __nv_bfloat16 g_Ehi[(size_t)VOCAB * EMBD];
__device__ __nv_bfloat16 g_Elo[(size_t)VOCAB * EMBD];
__device__ __nv_bfloat16 g_Hs[128 * RNN];               // [h_hi(64); h_lo(64)]
__device__ float g_zp[4][NB * Z4];                      // z partials (col' layout)
__device__ float g_c[NB * RNN];
__device__ float g_pooled[NB * RNN];
__device__ int   g_active[NT];
__device__ unsigned g_arrive;
__device__ int   g_release;

// ---------------- helpers --------------------------------------------------
__device__ __forceinline__ uint32_t smem_u32(const void* p) {
    return (uint32_t)__cvta_generic_to_shared(p);
}
__device__ __forceinline__ void cp_async16(uint32_t smem_dst, const void* gsrc) {
    asm volatile("cp.async.cg.shared.global [%0], [%1], 16;" :: "r"(smem_dst), "l"(gsrc));
}
#define CP_COMMIT() asm volatile("cp.async.commit_group;" ::: "memory")

__device__ __forceinline__ void ldsm_x4(uint32_t& r0, uint32_t& r1,
                                        uint32_t& r2, uint32_t& r3, uint32_t addr) {
    asm volatile("ldmatrix.sync.aligned.m8n8.x4.shared.b16 {%0,%1,%2,%3}, [%4];"
                 : "=r"(r0), "=r"(r1), "=r"(r2), "=r"(r3) : "r"(addr));
}
__device__ __forceinline__ void mma_bf16(float* c, uint32_t a0, uint32_t a1,
                                         uint32_t a2, uint32_t a3,
                                         uint32_t b0, uint32_t b1) {
    asm volatile("mma.sync.aligned.m16n8k16.row.col.f32.bf16.bf16.f32 "
                 "{%0,%1,%2,%3}, {%4,%5,%6,%7}, {%8,%9}, {%0,%1,%2,%3};"
                 : "+f"(c[0]), "+f"(c[1]), "+f"(c[2]), "+f"(c[3])
                 : "r"(a0), "r"(a1), "r"(a2), "r"(a3), "r"(b0), "r"(b1));
}

// ---------------- prep -----------------------------------------------------
__global__ void prep_kernel(const int* __restrict__ x) {
    int t = threadIdx.x;
    if (t < NT) {
        int act = 0;
        for (int b = 0; b < NB; b++) act |= (x[b * NT + t] != 0);
        g_active[t] = act;
    }
    if (t == 0) { g_arrive = 0; g_release = -1; }
}

__global__ void zero_kernel() {
    int i = blockIdx.x * blockDim.x + threadIdx.x;
    if (i < NB * RNN) {
        g_c[i] = 0.f; g_pooled[i] = 0.f;
        ((uint32_t*)g_Hs)[i] = 0u;
    }
}

// ---------------- emb split ------------------------------------------------
__global__ __launch_bounds__(256) void esplit_kernel(const float* __restrict__ emb) {
    size_t i = (size_t)blockIdx.x * 256 + threadIdx.x;
    float v = emb[i];
    __nv_bfloat16 hi = __float2bfloat16(v);
    g_Ehi[i] = hi;
    g_Elo[i] = __float2bfloat16(v - __bfloat162float(hi));
}

// ---------------- transpose+split+permute: U and W -------------------------
__device__ __forceinline__ int permute_col(int n) {
    return (n & 1023) * 4 + (n >> 10);
}

__global__ __launch_bounds__(256) void upack_kernel(const float* __restrict__ U) {
    __shared__ float tile[64][65];
    const int k0 = blockIdx.x * 64;
    const int n0 = blockIdx.y * 64;
    const int tid = threadIdx.x;
    #pragma unroll
    for (int it = 0; it < 16; it++) {
        int r = it * 4 + (tid >> 6);
        int c = tid & 63;
        tile[r][c] = U[(size_t)(k0 + r) * Z4 + n0 + c];
    }
    __syncthreads();
    #pragma unroll
    for (int it = 0; it < 16; it++) {
        int n = it * 4 + (tid >> 6);
        int k = tid & 63;
        float v = tile[k][n];
        __nv_bfloat16 hi = __float2bfloat16(v);
        const int np = permute_col(n0 + n);
        g_UThi[(size_t)np * RNN + k0 + k] = hi;
        g_UTlo[(size_t)np * RNN + k0 + k] =
            __float2bfloat16(v - __bfloat162float(hi));
    }
}

__global__ __launch_bounds__(256) void wpack_kernel(const float* __restrict__ W) {
    __shared__ float tile[64][65];
    const int k0 = blockIdx.x * 64;
    const int n0 = blockIdx.y * 64;
    const int tid = threadIdx.x;
    #pragma unroll
    for (int it = 0; it < 16; it++) {
        int r = it * 4 + (tid >> 6);
        int c = tid & 63;
        tile[r][c] = W[(size_t)(k0 + r) * Z4 + n0 + c];
    }
    __syncthreads();
    #pragma unroll
    for (int it = 0; it < 16; it++) {
        int n = it * 4 + (tid >> 6);
        int k = tid & 63;
        float v = tile[k][n];
        __nv_bfloat16 hi = __float2bfloat16(v);
        const int np = permute_col(n0 + n);
        g_WThi[(size_t)np * EMBD + k0 + k] = hi;
        g_WTlo[(size_t)np * EMBD + k0 + k] =
            __float2bfloat16(v - __bfloat162float(hi));
    }
}

// ---------------- shared GEMM config ----------------------------------------
#define BUF_BYTES 32768
#define GEMM_SMEM (1024 + 2 * BUF_BYTES)

// ---------------- HMMA input projection: XW[t] = emb[x_t] @ W --------------
#define XCHUNKS 16

__global__ __launch_bounds__(256) void xw_mma_kernel(const int* __restrict__ x) {
    const int t = blockIdx.y;
    if (!g_active[t]) return;

    extern __shared__ char dyn[];
    __shared__ int idxs[64];
    const uint32_t tb = (smem_u32(dyn) + 1023u) & ~1023u;

    const int tid  = threadIdx.x;
    const int w    = tid >> 5;
    const int lane = tid & 31;
    const int n0   = blockIdx.x * 128;
    const int mw   = w >> 1;
    const int nw   = w & 1;

    if (tid < 64) idxs[tid] = x[tid * NT + t];
    __syncthreads();

    float c[2][4][2][4];
    #pragma unroll
    for (int i = 0; i < 2; i++)
        #pragma unroll
        for (int j = 0; j < 4; j++)
            #pragma unroll
            for (int h = 0; h < 2; h++)
                #pragma unroll
                for (int r = 0; r < 4; r++) c[i][j][h][r] = 0.f;

    auto load_chunk = [&](int ch, int slot) {
        const uint32_t ab = tb + slot * BUF_BYTES;
        const uint32_t bb = ab + 16384;
        const int pass = ch >> 3;
        const int kg = (ch & 7) * 64;
        const __nv_bfloat16* Bsrc =
            (pass ? g_WTlo : g_WThi) + (size_t)n0 * EMBD + kg;
        #pragma unroll
        for (int r = 0; r < 4; r++) {
            const int o   = tid + 256 * r;
            const int row = o >> 3;
            const int cb  = o & 7;
            uint32_t off = (uint32_t)(row * 128 + cb * 16);
            uint32_t sw  = off ^ ((off >> 3) & 0x70);
            const __nv_bfloat16* asrc =
                (row < 64) ? (g_Ehi + (size_t)idxs[row] * EMBD + kg + cb * 8)
                           : (g_Elo + (size_t)idxs[row - 64] * EMBD + kg + cb * 8);
            cp_async16(ab + sw, asrc);
            cp_async16(bb + sw, Bsrc + (size_t)row * EMBD + cb * 8);
        }
        CP_COMMIT();
    };

    load_chunk(0, 0);

    const int lrow = ((lane >> 3) & 1) * 8 + (lane & 7);
    const int lcolb = (lane >> 4) * 16;

    for (int ch = 0; ch < XCHUNKS; ch++) {
        if (ch + 1 < XCHUNKS) load_chunk(ch + 1, (ch + 1) & 1);
        if (ch + 1 < XCHUNKS) asm volatile("cp.async.wait_group 1;" ::: "memory");
        else                  asm volatile("cp.async.wait_group 0;" ::: "memory");
        __syncthreads();

        const uint32_t ab = tb + (ch & 1) * BUF_BYTES;
        const uint32_t bb = ab + 16384;

        #pragma unroll
        for (int kk = 0; kk < 4; kk++) {
            uint32_t bf[4][4];
            #pragma unroll
            for (int nt = 0; nt < 4; nt++) {
                uint32_t boff = (uint32_t)((nw * 64 + nt * 16 + lrow) * 128 + kk * 32 + lcolb);
                uint32_t baddr = bb + (boff ^ ((boff >> 3) & 0x70));
                ldsm_x4(bf[nt][0], bf[nt][1], bf[nt][2], bf[nt][3], baddr);
            }
            #pragma unroll
            for (int mt = 0; mt < 2; mt++) {
                const int mbase = mt * 64 + mw * 16;
                uint32_t aoff = (uint32_t)((mbase + lrow) * 128 + kk * 32 + lcolb);
                uint32_t aaddr = ab + (aoff ^ ((aoff >> 3) & 0x70));
                uint32_t a0, a1, a2, a3;
                ldsm_x4(a0, a1, a2, a3, aaddr);
                #pragma unroll
                for (int nt = 0; nt < 4; nt++) {
                    mma_bf16(c[mt][nt][0], a0, a1, a2, a3, bf[nt][0], bf[nt][2]);
                    mma_bf16(c[mt][nt][1], a0, a1, a2, a3, bf[nt][1], bf[nt][3]);
                }
            }
        }
        __syncthreads();
    }

    float* C = g_XW + (size_t)t * NB * Z4;
    #pragma unroll
    for (int nt = 0; nt < 4; nt++) {
        #pragma unroll
        for (int h = 0; h < 2; h++) {
            const int row = mw * 16 + (lane >> 2);
            const int col = n0 + nw * 64 + nt * 16 + h * 8 + (lane & 3) * 2;
            float2 v01 = make_float2(c[0][nt][h][0] + c[1][nt][h][0],
                                     c[0][nt][h][1] + c[1][nt][h][1]);
            float2 v23 = make_float2(c[0][nt][h][2] + c[1][nt][h][2],
                                     c[0][nt][h][3] + c[1][nt][h][3]);
            *reinterpret_cast<float2*>(C + (size_t)row * Z4 + col) = v01;
            *reinterpret_cast<float2*>(C + (size_t)(row + 8) * Z4 + col) = v23;
        }
    }
}

// ---------------- per-step fused GEMM + grid-sync + wide cell ---------------
// grid (32 ng, 2 s, 2 ks) = 128 blocks x 256 thr. All blocks co-resident
// (128 <= 148 SMs). Barrier: release value = t (launch-unique).
#define ZCHUNKS 8

__global__ __launch_bounds__(256) void zstep_kernel(const int* __restrict__ x,
                                                    const float* __restrict__ bias, int t) {
    if (!g_active[t]) return;

    extern __shared__ char dyn[];
    const uint32_t tb = (smem_u32(dyn) + 1023u) & ~1023u;

    const int tid  = threadIdx.x;
    const int w    = tid >> 5;
    const int lane = tid & 31;
    const int ng   = blockIdx.x;
    const int n0   = ng * 128;
    const int s    = blockIdx.y;
    const int ks   = blockIdx.z;
    const int kbase = ks * 512;
    const int mw   = w >> 1;
    const int nw   = w & 1;

    const __nv_bfloat16* Bsrc = (s ? g_UTlo : g_UThi) + (size_t)n0 * RNN;

    float c[2][4][2][4];
    #pragma unroll
    for (int i = 0; i < 2; i++)
        #pragma unroll
        for (int j = 0; j < 4; j++)
            #pragma unroll
            for (int h = 0; h < 2; h++)
                #pragma unroll
                for (int r = 0; r < 4; r++) c[i][j][h][r] = 0.f;

    auto load_chunk = [&](int ch, int slot) {
        const uint32_t ab = tb + slot * BUF_BYTES;
        const uint32_t bb = ab + 16384;
        const int kg = kbase + ch * 64;
        #pragma unroll
        for (int r = 0; r < 4; r++) {
            const int o   = tid + 256 * r;
            const int row = o >> 3;
            const int cb  = o & 7;
            uint32_t off = (uint32_t)(row * 128 + cb * 16);
            uint32_t sw  = off ^ ((off >> 3) & 0x70);
            cp_async16(ab + sw, g_Hs + (size_t)row * RNN + kg + cb * 8);
            cp_async16(bb + sw, Bsrc + (size_t)row * RNN + kg + cb * 8);
        }
        CP_COMMIT();
    };

    load_chunk(0, 0);

    const int lrow = ((lane >> 3) & 1) * 8 + (lane & 7);
    const int lcolb = (lane >> 4) * 16;

    for (int ch = 0; ch < ZCHUNKS; ch++) {
        if (ch + 1 < ZCHUNKS) load_chunk(ch + 1, (ch + 1) & 1);
        if (ch + 1 < ZCHUNKS) asm volatile("cp.async.wait_group 1;" ::: "memory");
        else                  asm volatile("cp.async.wait_group 0;" ::: "memory");
        __syncthreads();

        const uint32_t ab = tb + (ch & 1) * BUF_BYTES;
        const uint32_t bb = ab + 16384;

        #pragma unroll
        for (int kk = 0; kk < 4; kk++) {
            uint32_t bf[4][4];
            #pragma unroll
            for (int nt = 0; nt < 4; nt++) {
                uint32_t boff = (uint32_t)((nw * 64 + nt * 16 + lrow) * 128 + kk * 32 + lcolb);
                uint32_t baddr = bb + (boff ^ ((boff >> 3) & 0x70));
                ldsm_x4(bf[nt][0], bf[nt][1], bf[nt][2], bf[nt][3], baddr);
            }
            #pragma unroll
            for (int mt = 0; mt < 2; mt++) {
                const int mbase = mt * 64 + mw * 16;
                uint32_t aoff = (uint32_t)((mbase + lrow) * 128 + kk * 32 + lcolb);
                uint32_t aaddr = ab + (aoff ^ ((aoff >> 3) & 0x70));
                uint32_t a0, a1, a2, a3;
                ldsm_x4(a0, a1, a2, a3, aaddr);
                #pragma unroll
                for (int nt = 0; nt < 4; nt++) {
                    mma_bf16(c[mt][nt][0], a0, a1, a2, a3, bf[nt][0], bf[nt][2]);
                    mma_bf16(c[mt][nt][1], a0, a1, a2, a3, bf[nt][1], bf[nt][3]);
                }
            }
        }
        __syncthreads();
    }

    // write partials (fold hi/lo rows)
    float* zb = g_zp[s * 2 + ks];
    #pragma unroll
    for (int nt = 0; nt < 4; nt++) {
        #pragma unroll
        for (int h = 0; h < 2; h++) {
            const int row = mw * 16 + (lane >> 2);
            const int col = n0 + nw * 64 + nt * 16 + h * 8 + (lane & 3) * 2;
            float2 v01 = make_float2(c[0][nt][h][0] + c[1][nt][h][0],
                                     c[0][nt][h][1] + c[1][nt][h][1]);
            float2 v23 = make_float2(c[0][nt][h][2] + c[1][nt][h][2],
                                     c[0][nt][h][3] + c[1][nt][h][3]);
            *reinterpret_cast<float2*>(zb + (size_t)row * Z4 + col) = v01;
            *reinterpret_cast<float2*>(zb + (size_t)(row + 8) * Z4 + col) = v23;
        }
    }

    // ---- grid barrier (128 blocks, release value = t) ----
    __threadfence();
    __syncthreads();
    if (tid == 0) {
        unsigned old = atomicAdd(&g_arrive, 1u);
        if (old == 127u) {
            g_arrive = 0;
            asm volatile("st.release.gpu.global.s32 [%0], %1;"
                         :: "l"(&g_release), "r"(t) : "memory");
        } else {
            int v;
            do {
                asm volatile("ld.acquire.gpu.global.s32 %0, [%1];"
                             : "=r"(v) : "l"(&g_release) : "memory");
            } while (v != t);
        }
    }
    __syncthreads();
    __threadfence();

    // ---- wide fused cell update: 128 blocks x 256 thr x 2 cells ----
    const int bid = ng + 32 * s + 64 * ks;   // 0..127
    #pragma unroll
    for (int r = 0; r < 2; r++) {
        const int cell = bid * 512 + r * 256 + tid;   // 0..65535
        const int b = cell >> 10;
        const int j = cell & 1023;
        const int cb = j * 4;                // col' base

        float4 zv = *reinterpret_cast<const float4*>(
            g_XW + ((size_t)t * NB + b) * Z4 + cb);
        #pragma unroll
        for (int p = 0; p < 4; p++) {
            float4 pv = *reinterpret_cast<const float4*>(
                g_zp[p] + (size_t)b * Z4 + cb);
            zv.x += pv.x; zv.y += pv.y; zv.z += pv.z; zv.w += pv.w;
        }
        const float zi = zv.x + bias[j];
        const float zf = zv.y + bias[RNN + j];
        const float zg = zv.z + bias[2 * RNN + j];
        const float zo = zv.w + bias[3 * RNN + j];

        const float si = 1.f / (1.f + expf(-zi));
        const float sf = 1.f / (1.f + expf(-zf));
        const float so = 1.f / (1.f + expf(-zo));
        const int gi = b * RNN + j;
        const float cn = sf * g_c[gi] + si * tanhf(zg);
        const float hn = so * tanhf(cn);
        const int xv = x[b * NT + t];
        if (xv != 0) {
            g_c[gi] = cn;
            __nv_bfloat16 hi = __float2bfloat16(hn);
            g_Hs[b * RNN + j] = hi;
            g_Hs[(b + 64) * RNN + j] = __float2bfloat16(hn - __bfloat162float(hi));
        }
        if (xv == 2) g_pooled[gi] += hn;
    }
}

// ---------------- head -----------------------------------------------------
__global__ __launch_bounds__(128) void head_kernel(const float* __restrict__ W1,
                                                   const float* __restrict__ b1,
                                                   const float* __restrict__ W2,
                                                   const float* __restrict__ b2,
                                                   const float* __restrict__ Wc,
                                                   const float* __restrict__ bc,
                                                   float* __restrict__ out) {
    const int b = blockIdx.x;
    const int tid = threadIdx.x;
    __shared__ float sp[RNN];
    __shared__ float h1s[HIDN];
    __shared__ float h2s[HIDN];
    __shared__ float lg[NLAB];

    for (int k = tid; k < RNN; k += 128) sp[k] = g_pooled[(size_t)b * RNN + k];
    __syncthreads();

    float a = b1[tid];
    for (int k = 0; k < RNN; k++) a += sp[k] * W1[(size_t)k * HIDN + tid];
    h1s[tid] = fmaxf(a, 0.f);
    __syncthreads();

    float a2 = b2[tid];
    for (int k = 0; k < HIDN; k++) a2 += h1s[k] * W2[(size_t)k * HIDN + tid];
    h2s[tid] = fmaxf(a2, 0.f);
    __syncthreads();

    if (tid < NLAB) {
        float l = bc[tid];
        for (int k = 0; k < HIDN; k++) l += h2s[k] * Wc[(size_t)k * NLAB + tid];
        lg[tid] = l;
    }
    __syncthreads();
    if (tid == 0) {
        const float mx = fmaxf(fmaxf(lg[0], lg[1]), fmaxf(lg[2], lg[3]));
        const float e0 = expf(lg[0] - mx), e1 = expf(lg[1] - mx);
        const float e2 = expf(lg[2] - mx), e3 = expf(lg[3] - mx);
        const float sden = e0 + e1 + e2 + e3;
        out[b * 4 + 0] = e0 / sden; out[b * 4 + 1] = e1 / sden;
        out[b * 4 + 2] = e2 / sden; out[b * 4 + 3] = e3 / sden;
    }
}

// ---------------- launcher -------------------------------------------------
extern "C" void kernel_launch(void* const* d_in, const int* in_sizes, int n_in,
                              void* d_out, int out_size) {
    const int*   x    = (const int*)d_in[0];
    const float* emb  = (const float*)d_in[1];
    const float* W    = (const float*)d_in[2];
    const float* U    = (const float*)d_in[3];
    const float* bias = (const float*)d_in[4];
    const float* W1   = (const float*)d_in[5];
    const float* b1   = (const float*)d_in[6];
    const float* W2   = (const float*)d_in[7];
    const float* b2   = (const float*)d_in[8];
    const float* Wc   = (const float*)d_in[9];
    const float* bc   = (const float*)d_in[10];
    float* out = (float*)d_out;

    cudaFuncSetAttribute(zstep_kernel, cudaFuncAttributeMaxDynamicSharedMemorySize, GEMM_SMEM);
    cudaFuncSetAttribute(xw_mma_kernel, cudaFuncAttributeMaxDynamicSharedMemorySize, GEMM_SMEM);

    prep_kernel<<<1, 256>>>(x);
    zero_kernel<<<256, 256>>>();
    esplit_kernel<<<(VOCAB * EMBD) / 256, 256>>>(emb);
    upack_kernel<<<dim3(RNN / 64, Z4 / 64), 256>>>(U);
    wpack_kernel<<<dim3(EMBD / 64, Z4 / 64), 256>>>(W);
    xw_mma_kernel<<<dim3(32, NT), 256, GEMM_SMEM>>>(x);
    for (int t = 0; t < NT; t++) {
        zstep_kernel<<<dim3(32, 2, 2), 256, GEMM_SMEM>>>(x, bias, t);
    }
    head_kernel<<<NB, 128>>>(W1, b1, W2, b2, Wc, bc, out);
}

// round 8
// speedup vs baseline: 1.2801x; 1.0335x over previous
#include <cuda_runtime.h>
#include <cuda_bf16.h>
#include <math.h>
#include <stdint.h>

#define NB   64
#define NT   256
#define EMBD 512
#define VOCAB 32000
#define RNN  1024
#define Z4   4096
#define HIDN 128
#define NLAB 4

// Column permutation: original n = gate*1024 + j  ->  col' = j*4 + gate.

// ---------------- static device scratch ----------------------------------
__device__ float g_XW[(size_t)NT * NB * Z4];            // emb[x] @ W  (col' layout)
__device__ __nv_bfloat16 g_UThi[(size_t)Z4 * RNN];      // U^T hi, [col'][k]
__device__ __nv_bfloat16 g_UTlo[(size_t)Z4 * RNN];
__device__ __nv_bfloat16 g_WThi[(size_t)Z4 * EMBD];
__device__ __nv_bfloat16 g_WTlo[(size_t)Z4 * EMBD];
__device__ __nv_bfloat16 g_Ehi[(size_t)VOCAB * EMBD];
__device__ __nv_bfloat16 g_Elo[(size_t)VOCAB * EMBD];
__device__ __nv_bfloat16 g_H2[2][128 * RNN];            // ping-pong [hi(64);lo(64)]
__device__ float g_zp2[2][NB * Z4];                     // split partials (col')
__device__ float g_c[NB * RNN];
__device__ float g_pooled[NB * RNN];
__device__ int   g_active[NT];
__device__ unsigned g_arrive;
__device__ int   g_release;

// ---------------- helpers --------------------------------------------------
__device__ __forceinline__ uint32_t smem_u32(const void* p) {
    return (uint32_t)__cvta_generic_to_shared(p);
}
__device__ __forceinline__ void cp_async16(uint32_t smem_dst, const void* gsrc) {
    asm volatile("cp.async.cg.shared.global [%0], [%1], 16;" :: "r"(smem_dst), "l"(gsrc));
}
#define CP_COMMIT() asm volatile("cp.async.commit_group;" ::: "memory")

__device__ __forceinline__ void ldsm_x4(uint32_t& r0, uint32_t& r1,
                                        uint32_t& r2, uint32_t& r3, uint32_t addr) {
    asm volatile("ldmatrix.sync.aligned.m8n8.x4.shared.b16 {%0,%1,%2,%3}, [%4];"
                 : "=r"(r0), "=r"(r1), "=r"(r2), "=r"(r3) : "r"(addr));
}
__device__ __forceinline__ void mma_bf16(float* c, uint32_t a0, uint32_t a1,
                                         uint32_t a2, uint32_t a3,
                                         uint32_t b0, uint32_t b1) {
    asm volatile("mma.sync.aligned.m16n8k16.row.col.f32.bf16.bf16.f32 "
                 "{%0,%1,%2,%3}, {%4,%5,%6,%7}, {%8,%9}, {%0,%1,%2,%3};"
                 : "+f"(c[0]), "+f"(c[1]), "+f"(c[2]), "+f"(c[3])
                 : "r"(a0), "r"(a1), "r"(a2), "r"(a3), "r"(b0), "r"(b1));
}

// ---------------- prep -----------------------------------------------------
__global__ void prep_kernel(const int* __restrict__ x) {
    int t = threadIdx.x;
    if (t < NT) {
        int act = 0;
        for (int b = 0; b < NB; b++) act |= (x[b * NT + t] != 0);
        g_active[t] = act;
    }
    if (t == 0) { g_arrive = 0; g_release = 0; }
}

__global__ void zero_kernel() {
    int i = blockIdx.x * blockDim.x + threadIdx.x;   // 512*256 = 131072
    if (i < NB * RNN) { g_c[i] = 0.f; g_pooled[i] = 0.f; }
    ((uint32_t*)g_H2)[i] = 0u;                       // 131072 u32 = both buffers
}

// ---------------- emb split ------------------------------------------------
__global__ __launch_bounds__(256) void esplit_kernel(const float* __restrict__ emb) {
    size_t i = (size_t)blockIdx.x * 256 + threadIdx.x;
    float v = emb[i];
    __nv_bfloat16 hi = __float2bfloat16(v);
    g_Ehi[i] = hi;
    g_Elo[i] = __float2bfloat16(v - __bfloat162float(hi));
}

// ---------------- transpose+split+permute: U and W -------------------------
__device__ __forceinline__ int permute_col(int n) {
    return (n & 1023) * 4 + (n >> 10);
}

__global__ __launch_bounds__(256) void upack_kernel(const float* __restrict__ U) {
    __shared__ float tile[64][65];
    const int k0 = blockIdx.x * 64;
    const int n0 = blockIdx.y * 64;
    const int tid = threadIdx.x;
    #pragma unroll
    for (int it = 0; it < 16; it++) {
        int r = it * 4 + (tid >> 6);
        int c = tid & 63;
        tile[r][c] = U[(size_t)(k0 + r) * Z4 + n0 + c];
    }
    __syncthreads();
    #pragma unroll
    for (int it = 0; it < 16; it++) {
        int n = it * 4 + (tid >> 6);
        int k = tid & 63;
        float v = tile[k][n];
        __nv_bfloat16 hi = __float2bfloat16(v);
        const int np = permute_col(n0 + n);
        g_UThi[(size_t)np * RNN + k0 + k] = hi;
        g_UTlo[(size_t)np * RNN + k0 + k] =
            __float2bfloat16(v - __bfloat162float(hi));
    }
}

__global__ __launch_bounds__(256) void wpack_kernel(const float* __restrict__ W) {
    __shared__ float tile[64][65];
    const int k0 = blockIdx.x * 64;
    const int n0 = blockIdx.y * 64;
    const int tid = threadIdx.x;
    #pragma unroll
    for (int it = 0; it < 16; it++) {
        int r = it * 4 + (tid >> 6);
        int c = tid & 63;
        tile[r][c] = W[(size_t)(k0 + r) * Z4 + n0 + c];
    }
    __syncthreads();
    #pragma unroll
    for (int it = 0; it < 16; it++) {
        int n = it * 4 + (tid >> 6);
        int k = tid & 63;
        float v = tile[k][n];
        __nv_bfloat16 hi = __float2bfloat16(v);
        const int np = permute_col(n0 + n);
        g_WThi[(size_t)np * EMBD + k0 + k] = hi;
        g_WTlo[(size_t)np * EMBD + k0 + k] =
            __float2bfloat16(v - __bfloat162float(hi));
    }
}

// ---------------- HMMA input projection (unchanged from R5) ----------------
#define BUF_BYTES 32768
#define GEMM_SMEM (1024 + 2 * BUF_BYTES)
#define XCHUNKS 16

__global__ __launch_bounds__(256) void xw_mma_kernel(const int* __restrict__ x) {
    const int t = blockIdx.y;
    if (!g_active[t]) return;

    extern __shared__ char dyn[];
    __shared__ int idxs[64];
    const uint32_t tb = (smem_u32(dyn) + 1023u) & ~1023u;

    const int tid  = threadIdx.x;
    const int w    = tid >> 5;
    const int lane = tid & 31;
    const int n0   = blockIdx.x * 128;
    const int mw   = w >> 1;
    const int nw   = w & 1;

    if (tid < 64) idxs[tid] = x[tid * NT + t];
    __syncthreads();

    float c[2][4][2][4];
    #pragma unroll
    for (int i = 0; i < 2; i++)
        #pragma unroll
        for (int j = 0; j < 4; j++)
            #pragma unroll
            for (int h = 0; h < 2; h++)
                #pragma unroll
                for (int r = 0; r < 4; r++) c[i][j][h][r] = 0.f;

    auto load_chunk = [&](int ch, int slot) {
        const uint32_t ab = tb + slot * BUF_BYTES;
        const uint32_t bb = ab + 16384;
        const int pass = ch >> 3;
        const int kg = (ch & 7) * 64;
        const __nv_bfloat16* Bsrc =
            (pass ? g_WTlo : g_WThi) + (size_t)n0 * EMBD + kg;
        #pragma unroll
        for (int r = 0; r < 4; r++) {
            const int o   = tid + 256 * r;
            const int row = o >> 3;
            const int cb  = o & 7;
            uint32_t off = (uint32_t)(row * 128 + cb * 16);
            uint32_t sw  = off ^ ((off >> 3) & 0x70);
            const __nv_bfloat16* asrc =
                (row < 64) ? (g_Ehi + (size_t)idxs[row] * EMBD + kg + cb * 8)
                           : (g_Elo + (size_t)idxs[row - 64] * EMBD + kg + cb * 8);
            cp_async16(ab + sw, asrc);
            cp_async16(bb + sw, Bsrc + (size_t)row * EMBD + cb * 8);
        }
        CP_COMMIT();
    };

    load_chunk(0, 0);

    const int lrow = ((lane >> 3) & 1) * 8 + (lane & 7);
    const int lcolb = (lane >> 4) * 16;

    for (int ch = 0; ch < XCHUNKS; ch++) {
        if (ch + 1 < XCHUNKS) load_chunk(ch + 1, (ch + 1) & 1);
        if (ch + 1 < XCHUNKS) asm volatile("cp.async.wait_group 1;" ::: "memory");
        else                  asm volatile("cp.async.wait_group 0;" ::: "memory");
        __syncthreads();

        const uint32_t ab = tb + (ch & 1) * BUF_BYTES;
        const uint32_t bb = ab + 16384;

        #pragma unroll
        for (int kk = 0; kk < 4; kk++) {
            uint32_t bf[4][4];
            #pragma unroll
            for (int nt = 0; nt < 4; nt++) {
                uint32_t boff = (uint32_t)((nw * 64 + nt * 16 + lrow) * 128 + kk * 32 + lcolb);
                uint32_t baddr = bb + (boff ^ ((boff >> 3) & 0x70));
                ldsm_x4(bf[nt][0], bf[nt][1], bf[nt][2], bf[nt][3], baddr);
            }
            #pragma unroll
            for (int mt = 0; mt < 2; mt++) {
                const int mbase = mt * 64 + mw * 16;
                uint32_t aoff = (uint32_t)((mbase + lrow) * 128 + kk * 32 + lcolb);
                uint32_t aaddr = ab + (aoff ^ ((aoff >> 3) & 0x70));
                uint32_t a0, a1, a2, a3;
                ldsm_x4(a0, a1, a2, a3, aaddr);
                #pragma unroll
                for (int nt = 0; nt < 4; nt++) {
                    mma_bf16(c[mt][nt][0], a0, a1, a2, a3, bf[nt][0], bf[nt][2]);
                    mma_bf16(c[mt][nt][1], a0, a1, a2, a3, bf[nt][1], bf[nt][3]);
                }
            }
        }
        __syncthreads();
    }

    float* C = g_XW + (size_t)t * NB * Z4;
    #pragma unroll
    for (int nt = 0; nt < 4; nt++) {
        #pragma unroll
        for (int h = 0; h < 2; h++) {
            const int row = mw * 16 + (lane >> 2);
            const int col = n0 + nw * 64 + nt * 16 + h * 8 + (lane & 3) * 2;
            float2 v01 = make_float2(c[0][nt][h][0] + c[1][nt][h][0],
                                     c[0][nt][h][1] + c[1][nt][h][1]);
            float2 v23 = make_float2(c[0][nt][h][2] + c[1][nt][h][2],
                                     c[0][nt][h][3] + c[1][nt][h][3]);
            *reinterpret_cast<float2*>(C + (size_t)row * Z4 + col) = v01;
            *reinterpret_cast<float2*>(C + (size_t)(row + 8) * Z4 + col) = v23;
        }
    }
}

// ---------------- persistent recurrence -------------------------------------
// 128 blocks x 256 thr, 1 CTA/SM. Block = (split s = bid>>6, n-slice bid&63).
// U slice resident in smem (128 KB); h streamed per step; 2 grid barriers/step.
#define RNN_SMEM (1024 + 131072 + 2 * 16384)

__global__ __launch_bounds__(256, 1) void rnn_persist(const int* __restrict__ x,
                                                      const float* __restrict__ bias) {
    extern __shared__ char dyn[];
    __shared__ int sact[NT];
    const uint32_t tb = (smem_u32(dyn) + 1023u) & ~1023u;   // B: 16 chunks x 8KB
    const uint32_t ab0 = tb + 131072;                       // A: 2 x 16KB

    const int tid  = threadIdx.x;
    const int w    = tid >> 5;
    const int lane = tid & 31;
    const int bid  = blockIdx.x;
    const int s    = bid >> 6;
    const int n0   = (bid & 63) * 64;
    const int mw   = w & 3;
    const int nw   = w >> 2;

    sact[tid] = g_active[tid];

    // ---- load U slice once: 16 chunks x (64 n-rows x 64 k) ----
    {
        const __nv_bfloat16* Bsrc = (s ? g_UTlo : g_UThi) + (size_t)n0 * RNN;
        #pragma unroll
        for (int r = 0; r < 32; r++) {
            const int o  = tid + 256 * r;      // 0..8191 16B-ops
            const int ch = o >> 9;             // 0..15
            const int n  = (o >> 3) & 63;
            const int cb = o & 7;
            uint32_t off = (uint32_t)(n * 128 + cb * 16);
            uint32_t sw  = off ^ ((off >> 3) & 0x70);
            cp_async16(tb + ch * 8192 + sw,
                       Bsrc + (size_t)n * RNN + ch * 64 + cb * 8);
        }
        CP_COMMIT();
        asm volatile("cp.async.wait_group 0;" ::: "memory");
    }
    __syncthreads();

    const int lrow = ((lane >> 3) & 1) * 8 + (lane & 7);
    const int lcolb = (lane >> 4) * 16;

    int epoch = 0;
    int rb = 0;

    for (int t = 0; t < NT; t++) {
        if (!sact[t]) continue;
        const __nv_bfloat16* Asrc = g_H2[rb];

        float c[2][2][2][4];
        #pragma unroll
        for (int i = 0; i < 2; i++)
            #pragma unroll
            for (int j = 0; j < 2; j++)
                #pragma unroll
                for (int h = 0; h < 2; h++)
                    #pragma unroll
                    for (int r = 0; r < 4; r++) c[i][j][h][r] = 0.f;

        auto load_a = [&](int ch, int slot) {
            const uint32_t ab = ab0 + slot * 16384;
            #pragma unroll
            for (int r = 0; r < 4; r++) {
                const int o   = tid + 256 * r;  // 0..1023
                const int row = o >> 3;
                const int cb  = o & 7;
                uint32_t off = (uint32_t)(row * 128 + cb * 16);
                uint32_t sw  = off ^ ((off >> 3) & 0x70);
                cp_async16(ab + sw, Asrc + (size_t)row * RNN + ch * 64 + cb * 8);
            }
            CP_COMMIT();
        };

        load_a(0, 0);

        for (int ch = 0; ch < 16; ch++) {
            if (ch + 1 < 16) load_a(ch + 1, (ch + 1) & 1);
            if (ch + 1 < 16) asm volatile("cp.async.wait_group 1;" ::: "memory");
            else             asm volatile("cp.async.wait_group 0;" ::: "memory");
            __syncthreads();

            const uint32_t ab = ab0 + (ch & 1) * 16384;
            const uint32_t bb = tb + ch * 8192;

            #pragma unroll
            for (int kk = 0; kk < 4; kk++) {
                uint32_t bf[2][4];
                #pragma unroll
                for (int nt = 0; nt < 2; nt++) {
                    uint32_t boff = (uint32_t)((nw * 32 + nt * 16 + lrow) * 128 + kk * 32 + lcolb);
                    uint32_t baddr = bb + (boff ^ ((boff >> 3) & 0x70));
                    ldsm_x4(bf[nt][0], bf[nt][1], bf[nt][2], bf[nt][3], baddr);
                }
                #pragma unroll
                for (int mt = 0; mt < 2; mt++) {
                    const int mbase = mt * 64 + mw * 16;
                    uint32_t aoff = (uint32_t)((mbase + lrow) * 128 + kk * 32 + lcolb);
                    uint32_t aaddr = ab + (aoff ^ ((aoff >> 3) & 0x70));
                    uint32_t a0, a1, a2, a3;
                    ldsm_x4(a0, a1, a2, a3, aaddr);
                    #pragma unroll
                    for (int nt = 0; nt < 2; nt++) {
                        mma_bf16(c[mt][nt][0], a0, a1, a2, a3, bf[nt][0], bf[nt][2]);
                        mma_bf16(c[mt][nt][1], a0, a1, a2, a3, bf[nt][1], bf[nt][3]);
                    }
                }
            }
            __syncthreads();
        }

        // epilogue: fold hi/lo, write split partial
        float* zb = g_zp2[s];
        #pragma unroll
        for (int nt = 0; nt < 2; nt++) {
            #pragma unroll
            for (int h = 0; h < 2; h++) {
                const int row = mw * 16 + (lane >> 2);
                const int col = n0 + nw * 32 + nt * 16 + h * 8 + (lane & 3) * 2;
                float2 v01 = make_float2(c[0][nt][h][0] + c[1][nt][h][0],
                                         c[0][nt][h][1] + c[1][nt][h][1]);
                float2 v23 = make_float2(c[0][nt][h][2] + c[1][nt][h][2],
                                         c[0][nt][h][3] + c[1][nt][h][3]);
                *reinterpret_cast<float2*>(zb + (size_t)row * Z4 + col) = v01;
                *reinterpret_cast<float2*>(zb + (size_t)(row + 8) * Z4 + col) = v23;
            }
        }

        // ---- barrier 1: all partials visible ----
        epoch++;
        __threadfence();
        __syncthreads();
        if (tid == 0) {
            unsigned old = atomicAdd(&g_arrive, 1u);
            if (old == 127u) {
                g_arrive = 0;
                asm volatile("st.release.gpu.global.s32 [%0], %1;"
                             :: "l"(&g_release), "r"(epoch) : "memory");
            } else {
                int v;
                do {
                    asm volatile("ld.acquire.gpu.global.s32 %0, [%1];"
                                 : "=r"(v) : "l"(&g_release) : "memory");
                } while (v < epoch);
            }
        }
        __syncthreads();
        __threadfence();

        // ---- wide cell update: 512 cells per block ----
        const __nv_bfloat16* hr = g_H2[rb];
        __nv_bfloat16* hw = g_H2[rb ^ 1];
        #pragma unroll
        for (int r = 0; r < 2; r++) {
            const int cell = bid * 512 + r * 256 + tid;
            const int b = cell >> 10;
            const int j = cell & 1023;
            const int cb = j * 4;

            float4 zv = *reinterpret_cast<const float4*>(
                g_XW + ((size_t)t * NB + b) * Z4 + cb);
            float4 p0 = *reinterpret_cast<const float4*>(g_zp2[0] + (size_t)b * Z4 + cb);
            float4 p1 = *reinterpret_cast<const float4*>(g_zp2[1] + (size_t)b * Z4 + cb);
            const float zi = zv.x + p0.x + p1.x + bias[j];
            const float zf = zv.y + p0.y + p1.y + bias[RNN + j];
            const float zg = zv.z + p0.z + p1.z + bias[2 * RNN + j];
            const float zo = zv.w + p0.w + p1.w + bias[3 * RNN + j];

            const float si = 1.f / (1.f + expf(-zi));
            const float sf = 1.f / (1.f + expf(-zf));
            const float so = 1.f / (1.f + expf(-zo));
            const int gi = b * RNN + j;
            const float cn = sf * g_c[gi] + si * tanhf(zg);
            const float hn = so * tanhf(cn);
            const int xv = x[b * NT + t];
            if (xv != 0) {
                g_c[gi] = cn;
                __nv_bfloat16 hi = __float2bfloat16(hn);
                hw[gi] = hi;
                hw[(b + 64) * RNN + j] = __float2bfloat16(hn - __bfloat162float(hi));
            } else {
                hw[gi] = hr[gi];
                hw[(b + 64) * RNN + j] = hr[(b + 64) * RNN + j];
            }
            if (xv == 2) g_pooled[gi] += hn;
        }

        // ---- barrier 2: h buffer ready ----
        epoch++;
        __threadfence();
        __syncthreads();
        if (tid == 0) {
            unsigned old = atomicAdd(&g_arrive, 1u);
            if (old == 127u) {
                g_arrive = 0;
                asm volatile("st.release.gpu.global.s32 [%0], %1;"
                             :: "l"(&g_release), "r"(epoch) : "memory");
            } else {
                int v;
                do {
                    asm volatile("ld.acquire.gpu.global.s32 %0, [%1];"
                                 : "=r"(v) : "l"(&g_release) : "memory");
                } while (v < epoch);
            }
        }
        __syncthreads();
        __threadfence();

        rb ^= 1;
    }
}

// ---------------- head -----------------------------------------------------
__global__ __launch_bounds__(128) void head_kernel(const float* __restrict__ W1,
                                                   const float* __restrict__ b1,
                                                   const float* __restrict__ W2,
                                                   const float* __restrict__ b2,
                                                   const float* __restrict__ Wc,
                                                   const float* __restrict__ bc,
                                                   float* __restrict__ out) {
    const int b = blockIdx.x;
    const int tid = threadIdx.x;
    __shared__ float sp[RNN];
    __shared__ float h1s[HIDN];
    __shared__ float h2s[HIDN];
    __shared__ float lg[NLAB];

    for (int k = tid; k < RNN; k += 128) sp[k] = g_pooled[(size_t)b * RNN + k];
    __syncthreads();

    float a = b1[tid];
    for (int k = 0; k < RNN; k++) a += sp[k] * W1[(size_t)k * HIDN + tid];
    h1s[tid] = fmaxf(a, 0.f);
    __syncthreads();

    float a2 = b2[tid];
    for (int k = 0; k < HIDN; k++) a2 += h1s[k] * W2[(size_t)k * HIDN + tid];
    h2s[tid] = fmaxf(a2, 0.f);
    __syncthreads();

    if (tid < NLAB) {
        float l = bc[tid];
        for (int k = 0; k < HIDN; k++) l += h2s[k] * Wc[(size_t)k * NLAB + tid];
        lg[tid] = l;
    }
    __syncthreads();
    if (tid == 0) {
        const float mx = fmaxf(fmaxf(lg[0], lg[1]), fmaxf(lg[2], lg[3]));
        const float e0 = expf(lg[0] - mx), e1 = expf(lg[1] - mx);
        const float e2 = expf(lg[2] - mx), e3 = expf(lg[3] - mx);
        const float sden = e0 + e1 + e2 + e3;
        out[b * 4 + 0] = e0 / sden; out[b * 4 + 1] = e1 / sden;
        out[b * 4 + 2] = e2 / sden; out[b * 4 + 3] = e3 / sden;
    }
}

// ---------------- launcher -------------------------------------------------
extern "C" void kernel_launch(void* const* d_in, const int* in_sizes, int n_in,
                              void* d_out, int out_size) {
    const int*   x    = (const int*)d_in[0];
    const float* emb  = (const float*)d_in[1];
    const float* W    = (const float*)d_in[2];
    const float* U    = (const float*)d_in[3];
    const float* bias = (const float*)d_in[4];
    const float* W1   = (const float*)d_in[5];
    const float* b1   = (const float*)d_in[6];
    const float* W2   = (const float*)d_in[7];
    const float* b2   = (const float*)d_in[8];
    const float* Wc   = (const float*)d_in[9];
    const float* bc   = (const float*)d_in[10];
    float* out = (float*)d_out;

    cudaFuncSetAttribute(xw_mma_kernel, cudaFuncAttributeMaxDynamicSharedMemorySize, GEMM_SMEM);
    cudaFuncSetAttribute(rnn_persist, cudaFuncAttributeMaxDynamicSharedMemorySize, RNN_SMEM);

    prep_kernel<<<1, 256>>>(x);
    zero_kernel<<<512, 256>>>();
    esplit_kernel<<<(VOCAB * EMBD) / 256, 256>>>(emb);
    upack_kernel<<<dim3(RNN / 64, Z4 / 64), 256>>>(U);
    wpack_kernel<<<dim3(EMBD / 64, Z4 / 64), 256>>>(W);
    xw_mma_kernel<<<dim3(32, NT), 256, GEMM_SMEM>>>(x);
    rnn_persist<<<128, 256, RNN_SMEM>>>(x, bias);
    head_kernel<<<NB, 128>>>(W1, b1, W2, b2, Wc, bc, out);
}